// round 12
// baseline (speedup 1.0000x reference)
#include <cuda_runtime.h>
#include <cstdint>

// Partitionable-threefry dropout (exact JAX match, rel_err = 0.0 confirmed):
//   bits[i] = fold(threefry2x32(key=(0,42), counter=(0,i))), fold = w0 ^ w1
//   keep    = bits < (7549747 << 9)
//   out[i]  = keep ? x[i] * (1/0.9) : 0,  cols [0,64) of each 4096-row -> 0
#define KS1 0x0000002Au
#define KS2 0x1BD11BF0u          // 0x1BD11BDA ^ 0 ^ 42

#define KEEP_CMP 0xE6666600u     // 7549747u << 9
#define DROP_SCALE ((float)(1.0 / 0.9))

__device__ __forceinline__ uint32_t rotl_shf(uint32_t x, int r) {
    return __funnelshift_l(x, x, r);   // SHF (alu pipe)
}

// Adds forced onto the fma pipe as IMAD (opaque multiplier `one` == 1).
__device__ __forceinline__ uint32_t fadd(uint32_t a, uint32_t b, uint32_t one) {
    uint32_t r;
    asm("mad.lo.u32 %0, %1, %2, %3;" : "=r"(r) : "r"(b), "r"(one), "r"(a));
    return r;
}
template <uint32_t C>
__device__ __forceinline__ uint32_t faddc(uint32_t a, uint32_t one) {
    uint32_t r;
    asm("mad.lo.u32 %0, %1, %2, %3;" : "=r"(r) : "r"(a), "r"(one), "n"(C));
    return r;
}

// Rotate on the fma pipe WITHOUT 64-bit pairs:
//   p = 2^r (warp-uniform runtime register -> UR file, not const-foldable)
//   lo = x * p (IMAD lo)        = x << r
//   hi = umulhi(x, p) (IMAD.HI) = x >> (32-r)
//   (lo | hi) ^ x0 fuses into ONE 3-input LOP3.
// Round cost: 1 alu + 3 fma (vs 2 alu + 1 fma for the SHF form).
__device__ __forceinline__ uint32_t rot_xor_mul(uint32_t x1, uint32_t x0, uint32_t p) {
    uint32_t lo;
    asm("mul.lo.u32 %0, %1, %2;" : "=r"(lo) : "r"(x1), "r"(p));
    uint32_t hi = __umulhi(x1, p);
    return (lo | hi) ^ x0;
}

// Full threefry2x32 block, c0 = 0, c1 = i, key (0,42); returns w0 ^ w1.
// 16 SHF rounds + 4 mul rounds (r1, r6, r11, r16):
// alu ~= 38/elem, fma ~= 38/elem, total ~= 77 -> w=4 is the analytic optimum
// of max(2*alu, total) over all SHF/mul splits.
__device__ __forceinline__ uint32_t threefry_fold(uint32_t i, uint32_t one,
                                                  uint32_t p13, uint32_t p29,
                                                  uint32_t p26, uint32_t p24) {
    uint32_t x1 = faddc<KS1>(i, one);       // x1 = i + 42
    uint32_t x0 = x1;                       // round-1 add folds (x0 was 0)
    x1 = rot_xor_mul(x1, x0, p13);                              // r1  M

    x0 = fadd(x0, x1, one); x1 = rotl_shf(x1, 15) ^ x0;         // r2
    x0 = fadd(x0, x1, one); x1 = rotl_shf(x1, 26) ^ x0;         // r3
    x0 = fadd(x0, x1, one); x1 = rotl_shf(x1,  6) ^ x0;         // r4
    x0 = faddc<KS1>(x0, one); x1 = faddc<KS2 + 1u>(x1, one);

    x0 = fadd(x0, x1, one); x1 = rotl_shf(x1, 17) ^ x0;         // r5
    x0 = fadd(x0, x1, one); x1 = rot_xor_mul(x1, x0, p29);      // r6  M
    x0 = fadd(x0, x1, one); x1 = rotl_shf(x1, 16) ^ x0;         // r7
    x0 = fadd(x0, x1, one); x1 = rotl_shf(x1, 24) ^ x0;         // r8
    x0 = faddc<KS2>(x0, one); x1 = faddc<2u>(x1, one);

    x0 = fadd(x0, x1, one); x1 = rotl_shf(x1, 13) ^ x0;         // r9
    x0 = fadd(x0, x1, one); x1 = rotl_shf(x1, 15) ^ x0;         // r10
    x0 = fadd(x0, x1, one); x1 = rot_xor_mul(x1, x0, p26);      // r11 M
    x0 = fadd(x0, x1, one); x1 = rotl_shf(x1,  6) ^ x0;         // r12
    /* x0 += KS0 == 0: skipped */ x1 = faddc<KS1 + 3u>(x1, one);

    x0 = fadd(x0, x1, one); x1 = rotl_shf(x1, 17) ^ x0;         // r13
    x0 = fadd(x0, x1, one); x1 = rotl_shf(x1, 29) ^ x0;         // r14
    x0 = fadd(x0, x1, one); x1 = rotl_shf(x1, 16) ^ x0;         // r15
    x0 = fadd(x0, x1, one); x1 = rot_xor_mul(x1, x0, p24);      // r16 M
    x0 = faddc<KS1>(x0, one); x1 = faddc<KS2 + 4u>(x1, one);

    x0 = fadd(x0, x1, one); x1 = rotl_shf(x1, 13) ^ x0;         // r17
    x0 = fadd(x0, x1, one); x1 = rotl_shf(x1, 15) ^ x0;         // r18
    x0 = fadd(x0, x1, one); x1 = rotl_shf(x1, 26) ^ x0;         // r19
    x0 = fadd(x0, x1, one); x1 = rotl_shf(x1,  6) ^ x0;         // r20
    x0 = faddc<KS2>(x0, one); x1 = faddc<5u>(x1, one);

    return x0 ^ x1;
}

// 8 consecutive elements per thread, ALL EIGHT chains in flight (ILP-8 —
// the best-measured config), forced to 32 regs / 8 blocks/SM via launch
// bounds. The four rotate multipliers are warp-uniform -> UR file, so they
// don't eat into the 32-reg budget. base is 8-aligned and 64 % 8 == 0, so
// the column-kill test (i & 4095) < 64 is uniform across the group.
__global__ void __launch_bounds__(256, 8)
dropout_threefry_part_kernel(const float* __restrict__ x,
                             float* __restrict__ out,
                             uint32_t one) {
    const uint32_t p13 = one << 13;
    const uint32_t p29 = one << 29;
    const uint32_t p26 = one << 26;
    const uint32_t p24 = one << 24;

    uint32_t base = (blockIdx.x * blockDim.x + threadIdx.x) * 8u;

    const float4 a = *reinterpret_cast<const float4*>(x + base);
    const float4 b = *reinterpret_cast<const float4*>(x + base + 4u);

    const float scale = ((base & 4095u) < 64u) ? 0.0f : DROP_SCALE;

    uint32_t bits[8];
#pragma unroll
    for (int j = 0; j < 8; ++j) {
        bits[j] = threefry_fold(base + (uint32_t)j, one, p13, p29, p26, p24);
    }

    // Predicated-multiply tail: ISETP + @p FMUL.
    float va[8] = {a.x, a.y, a.z, a.w, b.x, b.y, b.z, b.w};
    float r[8];
#pragma unroll
    for (int j = 0; j < 8; ++j) {
        float v = 0.0f;
        if (bits[j] < KEEP_CMP) v = va[j] * scale;
        r[j] = v;
    }

    float4 ra, rb;
    ra.x = r[0]; ra.y = r[1]; ra.z = r[2]; ra.w = r[3];
    rb.x = r[4]; rb.y = r[5]; rb.z = r[6]; rb.w = r[7];

    *reinterpret_cast<float4*>(out + base) = ra;
    *reinterpret_cast<float4*>(out + base + 4u) = rb;
}

extern "C" void kernel_launch(void* const* d_in, const int* in_sizes, int n_in,
                              void* d_out, int out_size) {
    const float* x = (const float*)d_in[0];
    float* out = (float*)d_out;

    const uint32_t n = (uint32_t)out_size;   // 16384 * 4096 = 2^26
    const int threads = 256;
    const uint32_t elems_per_block = threads * 8u;
    const int blocks = (int)((n + elems_per_block - 1) / elems_per_block);

    dropout_threefry_part_kernel<<<blocks, threads>>>(x, out, 1u);
}

// round 13
// speedup vs baseline: 1.0483x; 1.0483x over previous
#include <cuda_runtime.h>
#include <cstdint>

// Partitionable-threefry dropout (exact JAX match, rel_err = 0.0 confirmed):
//   bits[i] = fold(threefry2x32(key=(0,42), counter=(0,i))), fold = w0 ^ w1
//   keep    = bits < (7549747 << 9)   (== (bits>>9) < 0.9f*2^23, exact)
//   out[i]  = keep ? x[i] * (1/0.9) : 0,  cols [0,64) of each 4096-row -> 0
//
// Design note (rounds 4-12 exploration): the alu pipe (SHF+LOP3, 20 rounds
// x 2 ops) is the binder and runs at ~100% back-to-back efficiency when it
// is the SOLE saturated pipe. All attempts to offload rotates to the fma
// pipe (IMAD.WIDE / IMAD+IMAD.HI) lowered the paper bound but regressed in
// practice (mixed-issue efficiency ~80%, wide/hi ops half-rate). So: all
// rotates stay SHF, all integer adds go to the fma pipe as IMAD, and the
// tail uses predicated FMUL instead of FSEL to shave the last alu ops.
#define KS1 0x0000002Au
#define KS2 0x1BD11BF0u          // 0x1BD11BDA ^ 0 ^ 42

#define KEEP_CMP 0xE6666600u     // 7549747u << 9
#define DROP_SCALE ((float)(1.0 / 0.9))

__device__ __forceinline__ uint32_t rotl_shf(uint32_t x, int r) {
    return __funnelshift_l(x, x, r);   // SHF (alu pipe)
}

// Adds forced onto the fma pipe as IMAD (opaque multiplier `one` == 1).
__device__ __forceinline__ uint32_t fadd(uint32_t a, uint32_t b, uint32_t one) {
    uint32_t r;
    asm("mad.lo.u32 %0, %1, %2, %3;" : "=r"(r) : "r"(b), "r"(one), "r"(a));
    return r;
}
template <uint32_t C>
__device__ __forceinline__ uint32_t faddc(uint32_t a, uint32_t one) {
    uint32_t r;
    asm("mad.lo.u32 %0, %1, %2, %3;" : "=r"(r) : "r"(a), "r"(one), "n"(C));
    return r;
}

// Full threefry2x32 block, c0 = 0, c1 = i, key (0,42); returns w0 ^ w1.
// 20 SHF rounds; every add on the fma pipe. alu ~= 42/elem (the binder).
__device__ __forceinline__ uint32_t threefry_fold(uint32_t i, uint32_t one) {
    uint32_t x1 = faddc<KS1>(i, one);       // x1 = i + 42
    uint32_t x0 = x1;                       // round-1 add folds (x0 was 0)
    x1 = rotl_shf(x1, 13) ^ x0;                                 // r1

    x0 = fadd(x0, x1, one); x1 = rotl_shf(x1, 15) ^ x0;         // r2
    x0 = fadd(x0, x1, one); x1 = rotl_shf(x1, 26) ^ x0;         // r3
    x0 = fadd(x0, x1, one); x1 = rotl_shf(x1,  6) ^ x0;         // r4
    x0 = faddc<KS1>(x0, one); x1 = faddc<KS2 + 1u>(x1, one);

    x0 = fadd(x0, x1, one); x1 = rotl_shf(x1, 17) ^ x0;         // r5
    x0 = fadd(x0, x1, one); x1 = rotl_shf(x1, 29) ^ x0;         // r6
    x0 = fadd(x0, x1, one); x1 = rotl_shf(x1, 16) ^ x0;         // r7
    x0 = fadd(x0, x1, one); x1 = rotl_shf(x1, 24) ^ x0;         // r8
    x0 = faddc<KS2>(x0, one); x1 = faddc<2u>(x1, one);

    x0 = fadd(x0, x1, one); x1 = rotl_shf(x1, 13) ^ x0;         // r9
    x0 = fadd(x0, x1, one); x1 = rotl_shf(x1, 15) ^ x0;         // r10
    x0 = fadd(x0, x1, one); x1 = rotl_shf(x1, 26) ^ x0;         // r11
    x0 = fadd(x0, x1, one); x1 = rotl_shf(x1,  6) ^ x0;         // r12
    /* x0 += KS0 == 0: skipped */ x1 = faddc<KS1 + 3u>(x1, one);

    x0 = fadd(x0, x1, one); x1 = rotl_shf(x1, 17) ^ x0;         // r13
    x0 = fadd(x0, x1, one); x1 = rotl_shf(x1, 29) ^ x0;         // r14
    x0 = fadd(x0, x1, one); x1 = rotl_shf(x1, 16) ^ x0;         // r15
    x0 = fadd(x0, x1, one); x1 = rotl_shf(x1, 24) ^ x0;         // r16
    x0 = faddc<KS1>(x0, one); x1 = faddc<KS2 + 4u>(x1, one);

    x0 = fadd(x0, x1, one); x1 = rotl_shf(x1, 13) ^ x0;         // r17
    x0 = fadd(x0, x1, one); x1 = rotl_shf(x1, 15) ^ x0;         // r18
    x0 = fadd(x0, x1, one); x1 = rotl_shf(x1, 26) ^ x0;         // r19
    x0 = fadd(x0, x1, one); x1 = rotl_shf(x1,  6) ^ x0;         // r20
    x0 = faddc<KS2>(x0, one); x1 = faddc<5u>(x1, one);

    return x0 ^ x1;
}

// 8 consecutive elements per thread: two float4 loads/stores, 8 independent
// threefry chains for ILP (best-measured config: 32 regs, 8 blocks/SM at
// plain 256-thread launch bounds). base is 8-aligned and 64 % 8 == 0, so
// the column-kill test (i & 4095) < 64 is uniform across the group.
__global__ void __launch_bounds__(256)
dropout_threefry_part_kernel(const float* __restrict__ x,
                             float* __restrict__ out,
                             uint32_t one) {
    uint32_t base = (blockIdx.x * blockDim.x + threadIdx.x) * 8u;

    const float4 a = *reinterpret_cast<const float4*>(x + base);
    const float4 b = *reinterpret_cast<const float4*>(x + base + 4u);

    const float scale = ((base & 4095u) < 64u) ? 0.0f : DROP_SCALE;

    uint32_t bits[8];
#pragma unroll
    for (int j = 0; j < 8; ++j) {
        bits[j] = threefry_fold(base + (uint32_t)j, one);
    }

    // Predicated-multiply tail: ISETP + @p FMUL (no FSEL on the alu pipe).
    float va[8] = {a.x, a.y, a.z, a.w, b.x, b.y, b.z, b.w};
    float r[8];
#pragma unroll
    for (int j = 0; j < 8; ++j) {
        float v = 0.0f;
        if (bits[j] < KEEP_CMP) v = va[j] * scale;
        r[j] = v;
    }

    float4 ra, rb;
    ra.x = r[0]; ra.y = r[1]; ra.z = r[2]; ra.w = r[3];
    rb.x = r[4]; rb.y = r[5]; rb.z = r[6]; rb.w = r[7];

    *reinterpret_cast<float4*>(out + base) = ra;
    *reinterpret_cast<float4*>(out + base + 4u) = rb;
}

extern "C" void kernel_launch(void* const* d_in, const int* in_sizes, int n_in,
                              void* d_out, int out_size) {
    const float* x = (const float*)d_in[0];
    float* out = (float*)d_out;

    const uint32_t n = (uint32_t)out_size;   // 16384 * 4096 = 2^26
    const int threads = 256;
    const uint32_t elems_per_block = threads * 8u;
    const int blocks = (int)((n + elems_per_block - 1) / elems_per_block);

    dropout_threefry_part_kernel<<<blocks, threads>>>(x, out, 1u);
}

// round 15
// speedup vs baseline: 1.0534x; 1.0048x over previous
#include <cuda_runtime.h>
#include <cstdint>

// Partitionable-threefry dropout (exact JAX match, rel_err = 0.0 confirmed):
//   bits[i] = fold(threefry2x32(key=(0,42), counter=(0,i))), fold = w0 ^ w1
//   keep    = bits < (7549747 << 9)   (== (bits>>9) < 0.9f*2^23, exact)
//   out[i]  = keep ? x[i] * (1/0.9) : 0,  cols [0,64) of each 4096-row -> 0
//
// Design (locked in over rounds 4-13): all 20 rotates stay SHF (alu pipe),
// every integer add is forced onto the fma pipe as IMAD, tail is
// ISETP + predicated FMUL. The alu pipe is the sole saturated binder.
// This round: 16 elems/thread (two batches of 8 chains) to halve the
// per-thread fixed overhead, with a 40-reg budget for scheduling room.
#define KS1 0x0000002Au
#define KS2 0x1BD11BF0u          // 0x1BD11BDA ^ 0 ^ 42

#define KEEP_CMP 0xE6666600u     // 7549747u << 9
#define DROP_SCALE ((float)(1.0 / 0.9))

__device__ __forceinline__ uint32_t rotl_shf(uint32_t x, int r) {
    return __funnelshift_l(x, x, r);   // SHF (alu pipe)
}

// Adds forced onto the fma pipe as IMAD (opaque multiplier `one` == 1).
__device__ __forceinline__ uint32_t fadd(uint32_t a, uint32_t b, uint32_t one) {
    uint32_t r;
    asm("mad.lo.u32 %0, %1, %2, %3;" : "=r"(r) : "r"(b), "r"(one), "r"(a));
    return r;
}
template <uint32_t C>
__device__ __forceinline__ uint32_t faddc(uint32_t a, uint32_t one) {
    uint32_t r;
    asm("mad.lo.u32 %0, %1, %2, %3;" : "=r"(r) : "r"(a), "r"(one), "n"(C));
    return r;
}

// Full threefry2x32 block, c0 = 0, c1 = i, key (0,42); returns w0 ^ w1.
// 20 SHF rounds; every add on the fma pipe. alu ~= 2/round (the binder).
__device__ __forceinline__ uint32_t threefry_fold(uint32_t i, uint32_t one) {
    uint32_t x1 = faddc<KS1>(i, one);       // x1 = i + 42
    uint32_t x0 = x1;                       // round-1 add folds (x0 was 0)
    x1 = rotl_shf(x1, 13) ^ x0;                                 // r1

    x0 = fadd(x0, x1, one); x1 = rotl_shf(x1, 15) ^ x0;         // r2
    x0 = fadd(x0, x1, one); x1 = rotl_shf(x1, 26) ^ x0;         // r3
    x0 = fadd(x0, x1, one); x1 = rotl_shf(x1,  6) ^ x0;         // r4
    x0 = faddc<KS1>(x0, one); x1 = faddc<KS2 + 1u>(x1, one);

    x0 = fadd(x0, x1, one); x1 = rotl_shf(x1, 17) ^ x0;         // r5
    x0 = fadd(x0, x1, one); x1 = rotl_shf(x1, 29) ^ x0;         // r6
    x0 = fadd(x0, x1, one); x1 = rotl_shf(x1, 16) ^ x0;         // r7
    x0 = fadd(x0, x1, one); x1 = rotl_shf(x1, 24) ^ x0;         // r8
    x0 = faddc<KS2>(x0, one); x1 = faddc<2u>(x1, one);

    x0 = fadd(x0, x1, one); x1 = rotl_shf(x1, 13) ^ x0;         // r9
    x0 = fadd(x0, x1, one); x1 = rotl_shf(x1, 15) ^ x0;         // r10
    x0 = fadd(x0, x1, one); x1 = rotl_shf(x1, 26) ^ x0;         // r11
    x0 = fadd(x0, x1, one); x1 = rotl_shf(x1,  6) ^ x0;         // r12
    /* x0 += KS0 == 0: skipped */ x1 = faddc<KS1 + 3u>(x1, one);

    x0 = fadd(x0, x1, one); x1 = rotl_shf(x1, 17) ^ x0;         // r13
    x0 = fadd(x0, x1, one); x1 = rotl_shf(x1, 29) ^ x0;         // r14
    x0 = fadd(x0, x1, one); x1 = rotl_shf(x1, 16) ^ x0;         // r15
    x0 = fadd(x0, x1, one); x1 = rotl_shf(x1, 24) ^ x0;         // r16
    x0 = faddc<KS1>(x0, one); x1 = faddc<KS2 + 4u>(x1, one);

    x0 = fadd(x0, x1, one); x1 = rotl_shf(x1, 13) ^ x0;         // r17
    x0 = fadd(x0, x1, one); x1 = rotl_shf(x1, 15) ^ x0;         // r18
    x0 = fadd(x0, x1, one); x1 = rotl_shf(x1, 26) ^ x0;         // r19
    x0 = fadd(x0, x1, one); x1 = rotl_shf(x1,  6) ^ x0;         // r20
    x0 = faddc<KS2>(x0, one); x1 = faddc<5u>(x1, one);

    return x0 ^ x1;
}

// One batch: 8 consecutive elements (two float4s), 8 chains in flight.
__device__ __forceinline__ void do_batch8(uint32_t elem0, float4 a, float4 b,
                                          float scale, uint32_t one,
                                          float4* o0, float4* o1) {
    uint32_t bits[8];
#pragma unroll
    for (int j = 0; j < 8; ++j)
        bits[j] = threefry_fold(elem0 + (uint32_t)j, one);

    float va[8] = {a.x, a.y, a.z, a.w, b.x, b.y, b.z, b.w};
    float r[8];
#pragma unroll
    for (int j = 0; j < 8; ++j) {
        float v = 0.0f;
        if (bits[j] < KEEP_CMP) v = va[j] * scale;   // ISETP + @p FMUL
        r[j] = v;
    }

    float4 ra, rb;
    ra.x = r[0]; ra.y = r[1]; ra.z = r[2]; ra.w = r[3];
    rb.x = r[4]; rb.y = r[5]; rb.z = r[6]; rb.w = r[7];
    *o0 = ra;
    *o1 = rb;
}

// 16 consecutive elements per thread in two batches of 8 chains. base is
// 16-aligned and 64 % 16 == 0, so the column-kill test (i & 4095) < 64 is
// uniform across all 16 elements. 40-reg budget (6 blocks/SM) gives ptxas
// scheduling room between batches.
__global__ void __launch_bounds__(256, 6)
dropout_threefry_part_kernel(const float* __restrict__ x,
                             float* __restrict__ out,
                             uint32_t one) {
    uint32_t t = blockIdx.x * blockDim.x + threadIdx.x;
    uint32_t base = t * 16u;

    const float4* __restrict__ xp = reinterpret_cast<const float4*>(x) + t * 4u;
    float4* __restrict__ op = reinterpret_cast<float4*>(out) + t * 4u;

    const float scale = ((base & 4095u) < 64u) ? 0.0f : DROP_SCALE;

    // Batch 1: elements base+0 .. base+7
    {
        float4 a = xp[0];
        float4 b = xp[1];
        float4 ra, rb;
        do_batch8(base, a, b, scale, one, &ra, &rb);
        op[0] = ra;
        op[1] = rb;
    }
    // Batch 2: elements base+8 .. base+15
    {
        float4 a = xp[2];
        float4 b = xp[3];
        float4 ra, rb;
        do_batch8(base + 8u, a, b, scale, one, &ra, &rb);
        op[2] = ra;
        op[3] = rb;
    }
}

extern "C" void kernel_launch(void* const* d_in, const int* in_sizes, int n_in,
                              void* d_out, int out_size) {
    const float* x = (const float*)d_in[0];
    float* out = (float*)d_out;

    const uint32_t n = (uint32_t)out_size;   // 16384 * 4096 = 2^26
    const int threads = 256;
    const uint32_t elems_per_block = threads * 16u;
    const int blocks = (int)((n + elems_per_block - 1) / elems_per_block);

    dropout_threefry_part_kernel<<<blocks, threads>>>(x, out, 1u);
}